// round 15
// baseline (speedup 1.0000x reference)
#include <cuda_runtime.h>
#include <math.h>

#define T_  256
#define B_  32
#define E_  256
#define H_  512
#define V_  2048
#define TB_ 8192
#define G4H 2048

typedef unsigned long long ull;

// ---------------- static device scratch ----------------
__device__ float g_X[TB_ * 512];                  // [t*B+b][512]
__device__ float g_G[(size_t)T_ * G4H * B_];      // [t][n][b]  (pure ih-dot, no bias)
__device__ float g_Y0[(size_t)TB_ * H_];          // [t*B+b][512]  (layer-1 ih GEMM input)
__device__ float g_Y1[(size_t)TB_ * H_];          // [t][k][b]     (logits GEMM input)
__device__ float g_logits[(size_t)TB_ * V_];
__device__ float g_hbuf[2][2][H_][B_];            // [layer][ping][k][b]
__device__ float g_rowloss[TB_];
__device__ unsigned int g_cnt[2][8 * 32];         // 8 barrier counters/layer, 128B apart

// ---------------- f32x2 packed helpers ----------------
__device__ __forceinline__ void ffma2(ull& d, ull a, ull b) {
    asm("fma.rn.f32x2 %0, %1, %2, %0;" : "+l"(d) : "l"(a), "l"(b));
}
__device__ __forceinline__ ull pk2(float x, float y) {
    ull r; asm("mov.b64 %0, {%1,%2};" : "=l"(r) : "f"(x), "f"(y)); return r;
}
__device__ __forceinline__ float2 upk(ull v) {
    float2 r; asm("mov.b64 {%0,%1}, %2;" : "=f"(r.x), "=f"(r.y) : "l"(v)); return r;
}

// ---------------- XLA-matched fp32 nonlinearities ----------------
__device__ __forceinline__ float xla_tanhf(float x) {
    float ax = fabsf(x);
    float xc = fminf(fmaxf(x, -9.0f), 9.0f);
    float x2 = __fmul_rn(xc, xc);
    float p = -2.76076847742355e-16f;
    p = __fadd_rn(__fmul_rn(p, x2),  2.00018790482477e-13f);
    p = __fadd_rn(__fmul_rn(p, x2), -8.60467152213735e-11f);
    p = __fadd_rn(__fmul_rn(p, x2),  5.12229709037114e-08f);
    p = __fadd_rn(__fmul_rn(p, x2),  1.48572235717979e-05f);
    p = __fadd_rn(__fmul_rn(p, x2),  6.37261928875436e-04f);
    p = __fadd_rn(__fmul_rn(p, x2),  4.89352455891786e-03f);
    float np = __fmul_rn(xc, p);
    float q = 1.19825839466702e-06f;
    q = __fadd_rn(__fmul_rn(q, x2),  1.18534705686654e-04f);
    q = __fadd_rn(__fmul_rn(q, x2),  2.26843463243900e-03f);
    q = __fadd_rn(__fmul_rn(q, x2),  4.89352518554385e-03f);
    float r = __fdiv_rn(np, q);
    return (ax < 0.0004f) ? x : r;
}
__device__ __forceinline__ float xla_sigmoidf(float x) {
    return __fdiv_rn(1.0f, __fadd_rn(1.0f, expf(-x)));
}

// ---------------- no-op (keeps ncu -s 5 capture on gemm_ih #2) ----------------
__global__ void noop_kernel() {}

// ---------------- init ----------------
__global__ void init_kernel(const float* __restrict__ h0) {
    int idx = blockIdx.x * 256 + threadIdx.x;
    if (idx < 2 * 8 * 32) g_cnt[idx >> 8][idx & 255] = 0u;
    if (idx < 2 * H_ * B_) {
        int l = idx >> 14;
        int rem = idx & 16383;
        int k = rem >> 5, b = rem & 31;
        g_hbuf[l][0][k][b] = h0[(size_t)l * B_ * H_ + (size_t)b * H_ + k];
    }
}

// ---------------- embedding gather ----------------
__global__ void embed_kernel(const int* __restrict__ pc, const int* __restrict__ delta,
                             const float* __restrict__ pc_emb, const float* __restrict__ delta_emb) {
    int r = blockIdx.x;
    int i = threadIdx.x;
    float4* dst = (float4*)(g_X + (size_t)r * 512);
    if (i < 64) dst[i] = ((const float4*)(pc_emb + (size_t)pc[r] * E_))[i];
    else        dst[i] = ((const float4*)(delta_emb + (size_t)delta[r] * E_))[i - 64];
}

// ---------------- ih GEMM: G[t][n][b] = A . W^T, FFMA2, register-prefetch pipelined ----------------
__global__ void __launch_bounds__(256) gemm_ih_kernel(int which, const float* __restrict__ W) {
    const float* __restrict__ A = which ? g_Y0 : g_X;
    __shared__ float As[16][132];
    __shared__ float Bs[16][132];
    int tid = threadIdx.x;
    int tx = tid & 15, ty = tid >> 4;
    int bn = blockIdx.x * 128;
    int bm = blockIdx.y * 128;

    int row0 = tid >> 2,          c40 = (tid & 3) * 4;
    int row1 = (tid + 256) >> 2,  c41 = ((tid + 256) & 3) * 4;
    const float* a0p = A + (size_t)(bm + row0) * 512 + c40;
    const float* a1p = A + (size_t)(bm + row1) * 512 + c41;
    const float* b0p = W + (size_t)(bn + row0) * 512 + c40;
    const float* b1p = W + (size_t)(bn + row1) * 512 + c41;

    ull acc2[8][4];
#pragma unroll
    for (int i = 0; i < 8; i++)
#pragma unroll
        for (int j = 0; j < 4; j++) acc2[i][j] = 0ull;

    float4 pa0 = *(const float4*)(a0p);
    float4 pa1 = *(const float4*)(a1p);
    float4 pb0 = *(const float4*)(b0p);
    float4 pb1 = *(const float4*)(b1p);

    for (int it = 0; it < 32; it++) {
        As[c40 + 0][row0] = pa0.x; As[c40 + 1][row0] = pa0.y;
        As[c40 + 2][row0] = pa0.z; As[c40 + 3][row0] = pa0.w;
        As[c41 + 0][row1] = pa1.x; As[c41 + 1][row1] = pa1.y;
        As[c41 + 2][row1] = pa1.z; As[c41 + 3][row1] = pa1.w;
        Bs[c40 + 0][row0] = pb0.x; Bs[c40 + 1][row0] = pb0.y;
        Bs[c40 + 2][row0] = pb0.z; Bs[c40 + 3][row0] = pb0.w;
        Bs[c41 + 0][row1] = pb1.x; Bs[c41 + 1][row1] = pb1.y;
        Bs[c41 + 2][row1] = pb1.z; Bs[c41 + 3][row1] = pb1.w;
        if (it < 31) {
            int k0 = (it + 1) * 16;
            pa0 = *(const float4*)(a0p + k0);
            pa1 = *(const float4*)(a1p + k0);
            pb0 = *(const float4*)(b0p + k0);
            pb1 = *(const float4*)(b1p + k0);
        }
        __syncthreads();
#pragma unroll
        for (int kk = 0; kk < 16; kk++) {
            float4 a0 = *(const float4*)&As[kk][ty * 8];
            float4 a1 = *(const float4*)&As[kk][ty * 8 + 4];
            ulonglong2 b01 = *(const ulonglong2*)&Bs[kk][tx * 8];
            ulonglong2 b23 = *(const ulonglong2*)&Bs[kk][tx * 8 + 4];
            ull ap[8] = {pk2(a0.x, a0.x), pk2(a0.y, a0.y), pk2(a0.z, a0.z), pk2(a0.w, a0.w),
                         pk2(a1.x, a1.x), pk2(a1.y, a1.y), pk2(a1.z, a1.z), pk2(a1.w, a1.w)};
#pragma unroll
            for (int mi = 0; mi < 8; mi++) {
                ffma2(acc2[mi][0], ap[mi], b01.x);
                ffma2(acc2[mi][1], ap[mi], b01.y);
                ffma2(acc2[mi][2], ap[mi], b23.x);
                ffma2(acc2[mi][3], ap[mi], b23.y);
            }
        }
        __syncthreads();
    }

    float acc[8][8];
#pragma unroll
    for (int mi = 0; mi < 8; mi++)
#pragma unroll
        for (int jp = 0; jp < 4; jp++) {
            float2 f2 = upk(acc2[mi][jp]);
            acc[mi][2 * jp] = f2.x; acc[mi][2 * jp + 1] = f2.y;
        }

    int m0 = bm + ty * 8;
    int t = m0 >> 5;
    int b0 = m0 & 31;
#pragma unroll
    for (int nj = 0; nj < 8; nj++) {
        int n = bn + tx * 8 + nj;
        size_t base = ((size_t)t * G4H + n) * B_ + b0;
        float4 v0 = make_float4(acc[0][nj], acc[1][nj], acc[2][nj], acc[3][nj]);
        float4 v1 = make_float4(acc[4][nj], acc[5][nj], acc[6][nj], acc[7][nj]);
        *(float4*)(g_G + base) = v0;
        *(float4*)(g_G + base + 4) = v1;
    }
}

// ---------------- persistent LSTM layer: gate-major dot (4 dot warps + 4 helper warps) ----------------
// Dot warp q (0..3): hj = blk*4 + q, lane = b. Thread owns ALL 4 gates for (hj,b):
// 4 independent ascending-k FMA chains (bit-exact vs 2-gate split). No gate exchange needed.
// Helper warps (4..7): co-stage h, then gather G rows into smem during the dot.
__global__ void __launch_bounds__(256) lstm_kernel(const float* __restrict__ Whh,
                                                   const float* __restrict__ c0l,
                                                   int layer, int ylayout,
                                                   float* __restrict__ Y,
                                                   float* __restrict__ dout,
                                                   const float* __restrict__ bih,
                                                   const float* __restrict__ bhh) {
    extern __shared__ float sm[];
    float*  h_s = sm;                          // 16384 floats [k][b] (64KB)
    float4* wq  = (float4*)(sm + 16384);       // [hjl][k] -> {wi,wf,wg,wo}  (32KB)
    float*  Gs  = sm + 16384 + 8192;           // [(g*4+hjl)*32 + b] = 512 floats (2KB)

    float* hbuf = &g_hbuf[layer][0][0][0];
    unsigned int* cnt = &g_cnt[layer][0];

    int tid = threadIdx.x;
    int lane = tid & 31, q = tid >> 5;
    int hj = blockIdx.x * 4 + (q & 3);

    // pack wq once: entry (hjl,k) = {Whh[g*512+hj][k]}_{g=0..3}
    for (int e = tid; e < 2048; e += 256) {
        int hjl = e >> 9;
        int k = e & 511;
        int hjg = blockIdx.x * 4 + hjl;
        wq[hjl * 512 + k] = make_float4(
            Whh[((size_t)0 * 512 + hjg) * 512 + k],
            Whh[((size_t)1 * 512 + hjg) * 512 + k],
            Whh[((size_t)2 * 512 + hjg) * 512 + k],
            Whh[((size_t)3 * 512 + hjg) * 512 + k]);
    }

    // per-gate biases + c state (dot threads only)
    float bias_i = 0.f, bias_f = 0.f, bias_g = 0.f, bias_o = 0.f, c_r = 0.f;
    if (q < 4) {
        bias_i = __fadd_rn(bih[0 * 512 + hj], bhh[0 * 512 + hj]);
        bias_f = __fadd_rn(bih[1 * 512 + hj], bhh[1 * 512 + hj]);
        bias_g = __fadd_rn(bih[2 * 512 + hj], bhh[2 * 512 + hj]);
        bias_o = __fadd_rn(bih[3 * 512 + hj], bhh[3 * 512 + hj]);
        c_r = c0l[(size_t)lane * 512 + hj];
    }
    __syncthreads();

    const float4* wp = wq + (q & 3) * 512;
    int ping = 0;
    for (int t = 0; t < 256; t++) {
        // all 256 threads stage h (proven-overlapped float4 copy)
        const float* hsrc = hbuf + ping * 16384;
        for (int i = tid * 4; i < 16384; i += 1024)
            *(float4*)(h_s + i) = *(const float4*)(hsrc + i);
        __syncthreads();

        float ai = 0.f, af = 0.f, ag = 0.f, ao = 0.f;
        if (q < 4) {
            // dot: 4 ascending-k chains, h broadcast-free LDS.32, wq LDS.128 broadcast
#pragma unroll 4
            for (int k = 0; k < 512; k++) {
                float hv = h_s[k * 32 + lane];
                float4 w = wp[k];
                ai = fmaf(hv, w.x, ai);
                af = fmaf(hv, w.y, af);
                ag = fmaf(hv, w.z, ag);
                ao = fmaf(hv, w.w, ao);
            }
        } else {
            // helpers gather G rows for this step (concurrent with dot)
            int idx = tid - 128;           // 0..127
            int rr = idx >> 3;             // 0..15 : g = rr>>2, hjl = rr&3
            int part = idx & 7;
            int g = rr >> 2, hjl = rr & 3;
            *(float4*)&Gs[rr * 32 + part * 4] =
                *(const float4*)(g_G + ((size_t)t * G4H + (size_t)g * 512 + blockIdx.x * 4 + hjl) * B_ + part * 4);
        }
        __syncthreads();

        if (q < 4) {
            int hjl = q & 3;
            float Gi = Gs[(0 * 4 + hjl) * 32 + lane];
            float Gf = Gs[(1 * 4 + hjl) * 32 + lane];
            float Gg = Gs[(2 * 4 + hjl) * 32 + lane];
            float Go = Gs[(3 * 4 + hjl) * 32 + lane];
            float pre_i = __fadd_rn(__fadd_rn(Gi, ai), bias_i);
            float pre_f = __fadd_rn(__fadd_rn(Gf, af), bias_f);
            float pre_g = __fadd_rn(__fadd_rn(Gg, ag), bias_g);
            float pre_o = __fadd_rn(__fadd_rn(Go, ao), bias_o);
            float ig = xla_sigmoidf(pre_i);
            float fg = xla_sigmoidf(pre_f);
            float tg = xla_tanhf(pre_g);
            float og = xla_sigmoidf(pre_o);
            c_r = __fadd_rn(__fmul_rn(fg, c_r), __fmul_rn(ig, tg));
            float hn = __fmul_rn(og, xla_tanhf(c_r));

            hbuf[(ping ^ 1) * 16384 + hj * 32 + lane] = hn;
            if (ylayout) Y[(size_t)t * 16384 + hj * 32 + lane] = hn;
            else         Y[((size_t)t * 32 + lane) * 512 + hj] = hn;
            if (t == 255) {
                dout[81921  + (size_t)layer * 16384 + (size_t)lane * 512 + hj] = hn;
                dout[114689 + (size_t)layer * 16384 + (size_t)lane * 512 + hj] = c_r;
            }
        }
        // distributed barrier: 8 counters, every CTA polls all 8 (single round)
        __syncthreads();
        if (tid == 0) {
            __threadfence();
            atomicAdd(&cnt[(blockIdx.x & 7) * 32], 1u);
        }
        unsigned int target = 16u * (unsigned)(t + 1);
        if (tid < 8) {
            while (*(volatile unsigned int*)&cnt[tid * 32] < target) { }
            __threadfence();
        }
        __syncthreads();
        ping ^= 1;
    }
}

// ---------------- cluster-routed projection, FFMA2, register-prefetch pipelined ----------------
__global__ void __launch_bounds__(256) logits_kernel(const int* __restrict__ clusters,
                                                     const float* __restrict__ Wc,
                                                     const float* __restrict__ bc) {
    __shared__ float As[32][36];
    __shared__ float Bs[32][132];
    int tid = threadIdx.x;
    int t = blockIdx.y;
    int c = clusters[t];
    int n0 = blockIdx.x * 128;
    int tm = tid >> 5, tn = tid & 31;

    int kk_a = tid >> 3, mq = tid & 7;
    const float* ap = g_Y1 + (size_t)t * 16384 + (size_t)kk_a * 32 + mq * 4;
    int kk_b[4], c4_b[4];
    const float* bp4[4];
#pragma unroll
    for (int i = 0; i < 4; i++) {
        int idx = tid + i * 256;
        kk_b[i] = idx >> 5; c4_b[i] = (idx & 31) * 4;
        bp4[i] = Wc + ((size_t)c * 512 + kk_b[i]) * 2048 + n0 + c4_b[i];
    }

    ull acc2[4][2];
#pragma unroll
    for (int i = 0; i < 4; i++) { acc2[i][0] = 0ull; acc2[i][1] = 0ull; }

    float4 pa = *(const float4*)(ap);
    float4 pb[4];
#pragma unroll
    for (int i = 0; i < 4; i++) pb[i] = *(const float4*)(bp4[i]);

    for (int it = 0; it < 16; it++) {
        *(float4*)&As[kk_a][mq * 4] = pa;
#pragma unroll
        for (int i = 0; i < 4; i++) *(float4*)&Bs[kk_b[i]][c4_b[i]] = pb[i];
        if (it < 15) {
            int k0 = (it + 1) * 32;
            pa = *(const float4*)(ap + (size_t)k0 * 32);
#pragma unroll
            for (int i = 0; i < 4; i++) pb[i] = *(const float4*)(bp4[i] + (size_t)k0 * 2048);
        }
        __syncthreads();
#pragma unroll
        for (int kk = 0; kk < 32; kk++) {
            float4 a = *(const float4*)&As[kk][tm * 4];
            ulonglong2 bq = *(const ulonglong2*)&Bs[kk][tn * 4];
            ull ap0 = pk2(a.x, a.x), ap1 = pk2(a.y, a.y), ap2 = pk2(a.z, a.z), ap3 = pk2(a.w, a.w);
            ffma2(acc2[0][0], ap0, bq.x); ffma2(acc2[0][1], ap0, bq.y);
            ffma2(acc2[1][0], ap1, bq.x); ffma2(acc2[1][1], ap1, bq.y);
            ffma2(acc2[2][0], ap2, bq.x); ffma2(acc2[2][1], ap2, bq.y);
            ffma2(acc2[3][0], ap3, bq.x); ffma2(acc2[3][1], ap3, bq.y);
        }
        __syncthreads();
    }
#pragma unroll
    for (int mi = 0; mi < 4; mi++) {
        float2 x0 = upk(acc2[mi][0]), x1 = upk(acc2[mi][1]);
        int row = t * 32 + tm * 4 + mi;
        int col = n0 + tn * 4;
        float4 bv = *(const float4*)(bc + (size_t)c * 2048 + col);
        float4 v = make_float4(__fadd_rn(x0.x, bv.x), __fadd_rn(x0.y, bv.y),
                               __fadd_rn(x1.x, bv.z), __fadd_rn(x1.y, bv.w));
        *(float4*)(g_logits + (size_t)row * 2048 + col) = v;
    }
}

// ---------------- log-softmax + loss + top-10: warp-local top-10 + single merge ----------------
__global__ void __launch_bounds__(256) softmax_topk_kernel(const int* __restrict__ target,
                                                           float* __restrict__ dout) {
    int r = blockIdx.x;
    int tid = threadIdx.x;
    int lane = tid & 31, w = tid >> 5;
    const float* L = g_logits + (size_t)r * 2048;
    float v[8];
#pragma unroll
    for (int j = 0; j < 8; j++) v[j] = L[tid + j * 256];

    __shared__ float  sv[8];
    __shared__ double sd[8];
    __shared__ float  sbc;
    __shared__ float  cand_v[80];
    __shared__ int    cand_i[80];

    float m = -INFINITY;
#pragma unroll
    for (int j = 0; j < 8; j++) m = fmaxf(m, v[j]);
#pragma unroll
    for (int o = 16; o > 0; o >>= 1) m = fmaxf(m, __shfl_xor_sync(0xffffffffu, m, o));
    if (lane == 0) sv[w] = m;
    __syncthreads();
    if (tid == 0) {
        float mm = sv[0];
        for (int ww = 1; ww < 8; ww++) mm = fmaxf(mm, sv[ww]);
        sv[0] = mm;
    }
    __syncthreads();
    float M = sv[0];

    float sf[8];
    double s = 0.0;
#pragma unroll
    for (int j = 0; j < 8; j++) {
        sf[j] = __fadd_rn(v[j], -M);
        s += (double)expf(sf[j]);
    }
#pragma unroll
    for (int o = 16; o > 0; o >>= 1) s += __shfl_xor_sync(0xffffffffu, s, o);
    if (lane == 0) sd[w] = s;
    __syncthreads();
    if (tid == 0) {
        double ss = 0.0;
        for (int ww = 0; ww < 8; ww++) ss += sd[ww];
        double logS = log(ss);
        sbc = (float)logS;
        float sft = __fadd_rn(L[target[r]], -M);
        g_rowloss[r] = (float)(logS - (double)sft);
    }
    __syncthreads();
    float logS_f = sbc;

    float qv[8];
#pragma unroll
    for (int j = 0; j < 8; j++) qv[j] = __fadd_rn(sf[j], -logS_f);

    for (int it = 0; it < 10; it++) {
        float bv = -INFINITY;
        int bi = 1 << 30;
#pragma unroll
        for (int j = 0; j < 8; j++) {
            int gi = tid + j * 256;
            if (qv[j] > bv || (qv[j] == bv && gi < bi)) { bv = qv[j]; bi = gi; }
        }
#pragma unroll
        for (int o = 16; o > 0; o >>= 1) {
            float ov = __shfl_xor_sync(0xffffffffu, bv, o);
            int   oi = __shfl_xor_sync(0xffffffffu, bi, o);
            if (ov > bv || (ov == bv && oi < bi)) { bv = ov; bi = oi; }
        }
        if (lane == 0) { cand_v[w * 10 + it] = bv; cand_i[w * 10 + it] = bi; }
        if ((bi & 255) == tid) qv[bi >> 8] = -INFINITY;
    }
    __syncthreads();

    if (w == 0) {
        float cv[3];
        int   ci[3];
#pragma unroll
        for (int p = 0; p < 3; p++) {
            int idx = lane + p * 32;
            if (idx < 80) { cv[p] = cand_v[idx]; ci[p] = cand_i[idx]; }
            else          { cv[p] = -INFINITY;   ci[p] = 1 << 30; }
        }
        for (int it = 0; it < 10; it++) {
            float bv = -INFINITY;
            int bi = 1 << 30;
#pragma unroll
            for (int p = 0; p < 3; p++) {
                if (cv[p] > bv || (cv[p] == bv && ci[p] < bi)) { bv = cv[p]; bi = ci[p]; }
            }
#pragma unroll
            for (int o = 16; o > 0; o >>= 1) {
                float ov = __shfl_xor_sync(0xffffffffu, bv, o);
                int   oi = __shfl_xor_sync(0xffffffffu, bi, o);
                if (ov > bv || (ov == bv && oi < bi)) { bv = ov; bi = oi; }
            }
            if (lane == 0) dout[1 + (size_t)r * 10 + it] = (float)bi;
#pragma unroll
            for (int p = 0; p < 3; p++)
                if (ci[p] == bi) { cv[p] = -INFINITY; ci[p] = 1 << 30; }
        }
    }
}

// ---------------- deterministic loss reduction (double) ----------------
__global__ void __launch_bounds__(256) loss_kernel(float* __restrict__ dout) {
    __shared__ double s[256];
    int tid = threadIdx.x;
    double a = 0.0;
    for (int i = 0; i < 32; i++) a += (double)g_rowloss[tid * 32 + i];
    s[tid] = a;
    __syncthreads();
    for (int o = 128; o > 0; o >>= 1) {
        if (tid < o) s[tid] += s[tid + o];
        __syncthreads();
    }
    if (tid == 0) dout[0] = (float)(s[0] / 8192.0);
}

extern "C" void kernel_launch(void* const* d_in, const int* in_sizes, int n_in,
                              void* d_out, int out_size) {
    const int*   pc        = (const int*)d_in[0];
    const int*   delta     = (const int*)d_in[1];
    const int*   clusters  = (const int*)d_in[2];
    const int*   target    = (const int*)d_in[3];
    const float* h0        = (const float*)d_in[4];
    const float* c0        = (const float*)d_in[5];
    const float* pc_emb    = (const float*)d_in[6];
    const float* delta_emb = (const float*)d_in[7];
    const float* w_ih0     = (const float*)d_in[8];
    const float* w_hh0     = (const float*)d_in[9];
    const float* b_ih0     = (const float*)d_in[10];
    const float* b_hh0     = (const float*)d_in[11];
    const float* w_ih1     = (const float*)d_in[12];
    const float* w_hh1     = (const float*)d_in[13];
    const float* b_ih1     = (const float*)d_in[14];
    const float* b_hh1     = (const float*)d_in[15];
    const float* Wc        = (const float*)d_in[16];
    const float* bc        = (const float*)d_in[17];
    float* out = (float*)d_out;

    static int smem_set = 0;
    int lstm_smem = (16384 + 8192 + 512) * 4;   // h 64KB + wq 32KB + Gs 2KB
    if (!smem_set) {
        cudaFuncSetAttribute(lstm_kernel, cudaFuncAttributeMaxDynamicSharedMemorySize, lstm_smem);
        smem_set = 1;
    }

    float* g_Y0p = nullptr; float* g_Y1p = nullptr;
    cudaGetSymbolAddress((void**)&g_Y0p, g_Y0);
    cudaGetSymbolAddress((void**)&g_Y1p, g_Y1);

    noop_kernel<<<1, 32>>>();   // keeps ncu -s 5 capture on gemm_ih #2
    init_kernel<<<128, 256>>>(h0);
    embed_kernel<<<TB_, 128>>>(pc, delta, pc_emb, delta_emb);
    gemm_ih_kernel<<<dim3(16, 64), 256>>>(0, w_ih0);
    lstm_kernel<<<128, 256, lstm_smem>>>(w_hh0, c0, 0, 0, g_Y0p, out, b_ih0, b_hh0);
    gemm_ih_kernel<<<dim3(16, 64), 256>>>(1, w_ih1);
    lstm_kernel<<<128, 256, lstm_smem>>>(w_hh1, c0 + (size_t)B_ * H_, 1, 1, g_Y1p, out, b_ih1, b_hh1);
    logits_kernel<<<dim3(16, 256), 256>>>(clusters, Wc, bc);
    softmax_topk_kernel<<<TB_, 256>>>(target, out);
    loss_kernel<<<1, 256>>>(out);
}

// round 16
// speedup vs baseline: 1.5176x; 1.5176x over previous
#include <cuda_runtime.h>
#include <math.h>

#define T_  256
#define B_  32
#define E_  256
#define H_  512
#define V_  2048
#define TB_ 8192
#define G4H 2048

typedef unsigned long long ull;

// ---------------- static device scratch ----------------
__device__ float g_X[TB_ * 512];                  // [t*B+b][512]
__device__ float g_G[(size_t)T_ * G4H * B_];      // [t][n][b]  (pure ih-dot, no bias)
__device__ float g_Y0[(size_t)TB_ * H_];          // [t*B+b][512]  (layer-1 ih GEMM input)
__device__ float g_Y1[(size_t)TB_ * H_];          // [t][k][b]     (logits GEMM input)
__device__ float g_logits[(size_t)TB_ * V_];
__device__ float g_hbuf[2][2][H_][B_];            // [layer][ping][k][b]
__device__ float g_rowloss[TB_];
__device__ unsigned int g_cnt[2][8 * 32];         // 8 barrier counters/layer, 128B apart

// ---------------- f32x2 packed helpers ----------------
__device__ __forceinline__ void ffma2(ull& d, ull a, ull b) {
    asm("fma.rn.f32x2 %0, %1, %2, %0;" : "+l"(d) : "l"(a), "l"(b));
}
__device__ __forceinline__ ull pk2(float x, float y) {
    ull r; asm("mov.b64 %0, {%1,%2};" : "=l"(r) : "f"(x), "f"(y)); return r;
}
__device__ __forceinline__ float2 upk(ull v) {
    float2 r; asm("mov.b64 {%0,%1}, %2;" : "=f"(r.x), "=f"(r.y) : "l"(v)); return r;
}

// ---------------- XLA-matched fp32 nonlinearities ----------------
__device__ __forceinline__ float xla_tanhf(float x) {
    float ax = fabsf(x);
    float xc = fminf(fmaxf(x, -9.0f), 9.0f);
    float x2 = __fmul_rn(xc, xc);
    float p = -2.76076847742355e-16f;
    p = __fadd_rn(__fmul_rn(p, x2),  2.00018790482477e-13f);
    p = __fadd_rn(__fmul_rn(p, x2), -8.60467152213735e-11f);
    p = __fadd_rn(__fmul_rn(p, x2),  5.12229709037114e-08f);
    p = __fadd_rn(__fmul_rn(p, x2),  1.48572235717979e-05f);
    p = __fadd_rn(__fmul_rn(p, x2),  6.37261928875436e-04f);
    p = __fadd_rn(__fmul_rn(p, x2),  4.89352455891786e-03f);
    float np = __fmul_rn(xc, p);
    float q = 1.19825839466702e-06f;
    q = __fadd_rn(__fmul_rn(q, x2),  1.18534705686654e-04f);
    q = __fadd_rn(__fmul_rn(q, x2),  2.26843463243900e-03f);
    q = __fadd_rn(__fmul_rn(q, x2),  4.89352518554385e-03f);
    float r = __fdiv_rn(np, q);
    return (ax < 0.0004f) ? x : r;
}
__device__ __forceinline__ float xla_sigmoidf(float x) {
    return __fdiv_rn(1.0f, __fadd_rn(1.0f, expf(-x)));
}

// ---------------- init ----------------
__global__ void init_kernel(const float* __restrict__ h0) {
    int idx = blockIdx.x * 256 + threadIdx.x;
    if (idx < 2 * 8 * 32) g_cnt[idx >> 8][idx & 255] = 0u;
    if (idx < 2 * H_ * B_) {
        int l = idx >> 14;
        int rem = idx & 16383;
        int k = rem >> 5, b = rem & 31;
        g_hbuf[l][0][k][b] = h0[(size_t)l * B_ * H_ + (size_t)b * H_ + k];
    }
}

// ---------------- embedding gather ----------------
__global__ void embed_kernel(const int* __restrict__ pc, const int* __restrict__ delta,
                             const float* __restrict__ pc_emb, const float* __restrict__ delta_emb) {
    int r = blockIdx.x;
    int i = threadIdx.x;
    float4* dst = (float4*)(g_X + (size_t)r * 512);
    if (i < 64) dst[i] = ((const float4*)(pc_emb + (size_t)pc[r] * E_))[i];
    else        dst[i] = ((const float4*)(delta_emb + (size_t)delta[r] * E_))[i - 64];
}

// ---------------- ih GEMM: G[t][n][b] = A . W^T, FFMA2, register-prefetch pipelined ----------------
__global__ void __launch_bounds__(256) gemm_ih_kernel(int which, const float* __restrict__ W) {
    const float* __restrict__ A = which ? g_Y0 : g_X;
    __shared__ float As[16][132];
    __shared__ float Bs[16][132];
    int tid = threadIdx.x;
    int tx = tid & 15, ty = tid >> 4;
    int bn = blockIdx.x * 128;
    int bm = blockIdx.y * 128;

    int row0 = tid >> 2,          c40 = (tid & 3) * 4;
    int row1 = (tid + 256) >> 2,  c41 = ((tid + 256) & 3) * 4;
    const float* a0p = A + (size_t)(bm + row0) * 512 + c40;
    const float* a1p = A + (size_t)(bm + row1) * 512 + c41;
    const float* b0p = W + (size_t)(bn + row0) * 512 + c40;
    const float* b1p = W + (size_t)(bn + row1) * 512 + c41;

    ull acc2[8][4];
#pragma unroll
    for (int i = 0; i < 8; i++)
#pragma unroll
        for (int j = 0; j < 4; j++) acc2[i][j] = 0ull;

    float4 pa0 = *(const float4*)(a0p);
    float4 pa1 = *(const float4*)(a1p);
    float4 pb0 = *(const float4*)(b0p);
    float4 pb1 = *(const float4*)(b1p);

    for (int it = 0; it < 32; it++) {
        As[c40 + 0][row0] = pa0.x; As[c40 + 1][row0] = pa0.y;
        As[c40 + 2][row0] = pa0.z; As[c40 + 3][row0] = pa0.w;
        As[c41 + 0][row1] = pa1.x; As[c41 + 1][row1] = pa1.y;
        As[c41 + 2][row1] = pa1.z; As[c41 + 3][row1] = pa1.w;
        Bs[c40 + 0][row0] = pb0.x; Bs[c40 + 1][row0] = pb0.y;
        Bs[c40 + 2][row0] = pb0.z; Bs[c40 + 3][row0] = pb0.w;
        Bs[c41 + 0][row1] = pb1.x; Bs[c41 + 1][row1] = pb1.y;
        Bs[c41 + 2][row1] = pb1.z; Bs[c41 + 3][row1] = pb1.w;
        if (it < 31) {
            int k0 = (it + 1) * 16;
            pa0 = *(const float4*)(a0p + k0);
            pa1 = *(const float4*)(a1p + k0);
            pb0 = *(const float4*)(b0p + k0);
            pb1 = *(const float4*)(b1p + k0);
        }
        __syncthreads();
#pragma unroll
        for (int kk = 0; kk < 16; kk++) {
            float4 a0 = *(const float4*)&As[kk][ty * 8];
            float4 a1 = *(const float4*)&As[kk][ty * 8 + 4];
            ulonglong2 b01 = *(const ulonglong2*)&Bs[kk][tx * 8];
            ulonglong2 b23 = *(const ulonglong2*)&Bs[kk][tx * 8 + 4];
            ull ap[8] = {pk2(a0.x, a0.x), pk2(a0.y, a0.y), pk2(a0.z, a0.z), pk2(a0.w, a0.w),
                         pk2(a1.x, a1.x), pk2(a1.y, a1.y), pk2(a1.z, a1.z), pk2(a1.w, a1.w)};
#pragma unroll
            for (int mi = 0; mi < 8; mi++) {
                ffma2(acc2[mi][0], ap[mi], b01.x);
                ffma2(acc2[mi][1], ap[mi], b01.y);
                ffma2(acc2[mi][2], ap[mi], b23.x);
                ffma2(acc2[mi][3], ap[mi], b23.y);
            }
        }
        __syncthreads();
    }

    float acc[8][8];
#pragma unroll
    for (int mi = 0; mi < 8; mi++)
#pragma unroll
        for (int jp = 0; jp < 4; jp++) {
            float2 f2 = upk(acc2[mi][jp]);
            acc[mi][2 * jp] = f2.x; acc[mi][2 * jp + 1] = f2.y;
        }

    int m0 = bm + ty * 8;
    int t = m0 >> 5;
    int b0 = m0 & 31;
#pragma unroll
    for (int nj = 0; nj < 8; nj++) {
        int n = bn + tx * 8 + nj;
        size_t base = ((size_t)t * G4H + n) * B_ + b0;
        float4 v0 = make_float4(acc[0][nj], acc[1][nj], acc[2][nj], acc[3][nj]);
        float4 v1 = make_float4(acc[4][nj], acc[5][nj], acc[6][nj], acc[7][nj]);
        *(float4*)(g_G + base) = v0;
        *(float4*)(g_G + base + 4) = v1;
    }
}

// ---------------- persistent LSTM layer (round-12 proven form; G-load hoisted) ----------------
__global__ void __launch_bounds__(256) lstm_kernel(const float* __restrict__ Whh,
                                                   const float* __restrict__ c0l,
                                                   int layer, int ylayout,
                                                   float* __restrict__ Y,
                                                   float* __restrict__ dout,
                                                   const float* __restrict__ bih,
                                                   const float* __restrict__ bhh) {
    extern __shared__ float sm[];
    float* h_s = sm;                 // 16384 floats [k][b]
    float* w_s = sm + 16384;         // 8192 : 16 rows (hl*4+g) x 512
    float* ex  = sm + 24576;         // 256  : [hjl*32+b]*2
    float* c_s = sm + 24832;         // 128

    float* hbuf = &g_hbuf[layer][0][0][0];
    unsigned int* cnt = &g_cnt[layer][0];

    int tid = threadIdx.x;
    int b = tid & 31, q = tid >> 5;
    int hjl = q & 3;
    int hj = blockIdx.x * 4 + hjl;
    int gbase = (q < 4) ? 0 : 2;     // gates (i,f) or (g,o)

    for (int i = tid; i < 2048; i += 256) {      // 2048 float4 of W_hh slice
        int r = i >> 7;
        int c4 = (i & 127) * 4;
        int g = r & 3, hl = r >> 2;
        *(float4*)(w_s + r * 512 + c4) =
            *(const float4*)(Whh + ((size_t)g * 512 + blockIdx.x * 4 + hl) * 512 + c4);
    }
    if (tid < 128) {
        int hl = tid >> 5, bb = tid & 31;
        c_s[hl * 32 + bb] = c0l[(size_t)bb * 512 + blockIdx.x * 4 + hl];
    }
    const float* w0 = w_s + (hjl * 4 + gbase) * 512;
    const float* w1 = w0 + 512;
    int n0g = gbase * 512 + hj;
    int n1g = (gbase + 1) * 512 + hj;
    float bias0 = __fadd_rn(bih[n0g], bhh[n0g]);
    float bias1 = __fadd_rn(bih[n1g], bhh[n1g]);
    __syncthreads();

    int ping = 0;
    for (int t = 0; t < 256; t++) {
        // G load hoisted: independent of staged h, latency hides under staging+sync
        float G0 = g_G[((size_t)t * G4H + n0g) * B_ + b];
        float G1 = g_G[((size_t)t * G4H + n1g) * B_ + b];

        const float* hsrc = hbuf + ping * 16384;
        for (int i = tid * 4; i < 16384; i += 1024)
            *(float4*)(h_s + i) = *(const float4*)(hsrc + i);
        __syncthreads();

        float acc0 = 0.0f, acc1 = 0.0f;
#pragma unroll 4
        for (int k = 0; k < 512; k += 4) {
            float4 wa = *(const float4*)(w0 + k);
            float4 wb = *(const float4*)(w1 + k);
            float h0v = h_s[(k + 0) * 32 + b];
            float h1v = h_s[(k + 1) * 32 + b];
            float h2v = h_s[(k + 2) * 32 + b];
            float h3v = h_s[(k + 3) * 32 + b];
            acc0 = fmaf(h0v, wa.x, acc0); acc1 = fmaf(h0v, wb.x, acc1);
            acc0 = fmaf(h1v, wa.y, acc0); acc1 = fmaf(h1v, wb.y, acc1);
            acc0 = fmaf(h2v, wa.z, acc0); acc1 = fmaf(h2v, wb.z, acc1);
            acc0 = fmaf(h3v, wa.w, acc0); acc1 = fmaf(h3v, wb.w, acc1);
        }

        float pre0 = __fadd_rn(__fadd_rn(G0, acc0), bias0);
        float pre1 = __fadd_rn(__fadd_rn(G1, acc1), bias1);

        if (q >= 4) {                 // g, o pre-activations
            ex[(hjl * 32 + b) * 2 + 0] = pre0;
            ex[(hjl * 32 + b) * 2 + 1] = pre1;
        }
        __syncthreads();
        if (q < 4) {                  // i=pre0, f=pre1
            float pre_g = ex[(hjl * 32 + b) * 2 + 0];
            float pre_o = ex[(hjl * 32 + b) * 2 + 1];
            float ig = xla_sigmoidf(pre0);
            float fg = xla_sigmoidf(pre1);
            float tg = xla_tanhf(pre_g);
            float og = xla_sigmoidf(pre_o);
            float cold = c_s[hjl * 32 + b];
            float cn = __fadd_rn(__fmul_rn(fg, cold), __fmul_rn(ig, tg));
            float hn = __fmul_rn(og, xla_tanhf(cn));
            c_s[hjl * 32 + b] = cn;
            hbuf[(ping ^ 1) * 16384 + hj * 32 + b] = hn;
            if (ylayout) Y[(size_t)t * 16384 + hj * 32 + b] = hn;
            else         Y[((size_t)t * 32 + b) * 512 + hj] = hn;
            if (t == 255) {
                dout[81921  + (size_t)layer * 16384 + (size_t)b * 512 + hj] = hn;
                dout[114689 + (size_t)layer * 16384 + (size_t)b * 512 + hj] = cn;
            }
        }
        // distributed barrier: 8 counters, every CTA polls all 8 (single round)
        __syncthreads();
        if (tid == 0) {
            __threadfence();
            atomicAdd(&cnt[(blockIdx.x & 7) * 32], 1u);
        }
        unsigned int target = 16u * (unsigned)(t + 1);
        if (tid < 8) {
            while (*(volatile unsigned int*)&cnt[tid * 32] < target) { }
            __threadfence();
        }
        __syncthreads();
        ping ^= 1;
    }
}

// ---------------- cluster-routed projection, FFMA2, register-prefetch pipelined ----------------
__global__ void __launch_bounds__(256) logits_kernel(const int* __restrict__ clusters,
                                                     const float* __restrict__ Wc,
                                                     const float* __restrict__ bc) {
    __shared__ float As[32][36];
    __shared__ float Bs[32][132];
    int tid = threadIdx.x;
    int t = blockIdx.y;
    int c = clusters[t];
    int n0 = blockIdx.x * 128;
    int tm = tid >> 5, tn = tid & 31;

    int kk_a = tid >> 3, mq = tid & 7;
    const float* ap = g_Y1 + (size_t)t * 16384 + (size_t)kk_a * 32 + mq * 4;
    int kk_b[4], c4_b[4];
    const float* bp4[4];
#pragma unroll
    for (int i = 0; i < 4; i++) {
        int idx = tid + i * 256;
        kk_b[i] = idx >> 5; c4_b[i] = (idx & 31) * 4;
        bp4[i] = Wc + ((size_t)c * 512 + kk_b[i]) * 2048 + n0 + c4_b[i];
    }

    ull acc2[4][2];
#pragma unroll
    for (int i = 0; i < 4; i++) { acc2[i][0] = 0ull; acc2[i][1] = 0ull; }

    float4 pa = *(const float4*)(ap);
    float4 pb[4];
#pragma unroll
    for (int i = 0; i < 4; i++) pb[i] = *(const float4*)(bp4[i]);

    for (int it = 0; it < 16; it++) {
        *(float4*)&As[kk_a][mq * 4] = pa;
#pragma unroll
        for (int i = 0; i < 4; i++) *(float4*)&Bs[kk_b[i]][c4_b[i]] = pb[i];
        if (it < 15) {
            int k0 = (it + 1) * 32;
            pa = *(const float4*)(ap + (size_t)k0 * 32);
#pragma unroll
            for (int i = 0; i < 4; i++) pb[i] = *(const float4*)(bp4[i] + (size_t)k0 * 2048);
        }
        __syncthreads();
#pragma unroll
        for (int kk = 0; kk < 32; kk++) {
            float4 a = *(const float4*)&As[kk][tm * 4];
            ulonglong2 bq = *(const ulonglong2*)&Bs[kk][tn * 4];
            ull ap0 = pk2(a.x, a.x), ap1 = pk2(a.y, a.y), ap2 = pk2(a.z, a.z), ap3 = pk2(a.w, a.w);
            ffma2(acc2[0][0], ap0, bq.x); ffma2(acc2[0][1], ap0, bq.y);
            ffma2(acc2[1][0], ap1, bq.x); ffma2(acc2[1][1], ap1, bq.y);
            ffma2(acc2[2][0], ap2, bq.x); ffma2(acc2[2][1], ap2, bq.y);
            ffma2(acc2[3][0], ap3, bq.x); ffma2(acc2[3][1], ap3, bq.y);
        }
        __syncthreads();
    }
#pragma unroll
    for (int mi = 0; mi < 4; mi++) {
        float2 x0 = upk(acc2[mi][0]), x1 = upk(acc2[mi][1]);
        int row = t * 32 + tm * 4 + mi;
        int col = n0 + tn * 4;
        float4 bv = *(const float4*)(bc + (size_t)c * 2048 + col);
        float4 v = make_float4(__fadd_rn(x0.x, bv.x), __fadd_rn(x0.y, bv.y),
                               __fadd_rn(x1.x, bv.z), __fadd_rn(x1.y, bv.w));
        *(float4*)(g_logits + (size_t)row * 2048 + col) = v;
    }
}

// ---------------- log-softmax + loss + top-10: warp-local top-10 + single merge ----------------
__global__ void __launch_bounds__(256) softmax_topk_kernel(const int* __restrict__ target,
                                                           float* __restrict__ dout) {
    int r = blockIdx.x;
    int tid = threadIdx.x;
    int lane = tid & 31, w = tid >> 5;
    const float* L = g_logits + (size_t)r * 2048;
    float v[8];
#pragma unroll
    for (int j = 0; j < 8; j++) v[j] = L[tid + j * 256];

    __shared__ float  sv[8];
    __shared__ double sd[8];
    __shared__ float  sbc;
    __shared__ float  cand_v[80];
    __shared__ int    cand_i[80];

    float m = -INFINITY;
#pragma unroll
    for (int j = 0; j < 8; j++) m = fmaxf(m, v[j]);
#pragma unroll
    for (int o = 16; o > 0; o >>= 1) m = fmaxf(m, __shfl_xor_sync(0xffffffffu, m, o));
    if (lane == 0) sv[w] = m;
    __syncthreads();
    if (tid == 0) {
        float mm = sv[0];
        for (int ww = 1; ww < 8; ww++) mm = fmaxf(mm, sv[ww]);
        sv[0] = mm;
    }
    __syncthreads();
    float M = sv[0];

    float sf[8];
    double s = 0.0;
#pragma unroll
    for (int j = 0; j < 8; j++) {
        sf[j] = __fadd_rn(v[j], -M);
        s += (double)expf(sf[j]);
    }
#pragma unroll
    for (int o = 16; o > 0; o >>= 1) s += __shfl_xor_sync(0xffffffffu, s, o);
    if (lane == 0) sd[w] = s;
    __syncthreads();
    if (tid == 0) {
        double ss = 0.0;
        for (int ww = 0; ww < 8; ww++) ss += sd[ww];
        double logS = log(ss);
        sbc = (float)logS;
        float sft = __fadd_rn(L[target[r]], -M);
        g_rowloss[r] = (float)(logS - (double)sft);
    }
    __syncthreads();
    float logS_f = sbc;

    float qv[8];
#pragma unroll
    for (int j = 0; j < 8; j++) qv[j] = __fadd_rn(sf[j], -logS_f);

    for (int it = 0; it < 10; it++) {
        float bv = -INFINITY;
        int bi = 1 << 30;
#pragma unroll
        for (int j = 0; j < 8; j++) {
            int gi = tid + j * 256;
            if (qv[j] > bv || (qv[j] == bv && gi < bi)) { bv = qv[j]; bi = gi; }
        }
#pragma unroll
        for (int o = 16; o > 0; o >>= 1) {
            float ov = __shfl_xor_sync(0xffffffffu, bv, o);
            int   oi = __shfl_xor_sync(0xffffffffu, bi, o);
            if (ov > bv || (ov == bv && oi < bi)) { bv = ov; bi = oi; }
        }
        if (lane == 0) { cand_v[w * 10 + it] = bv; cand_i[w * 10 + it] = bi; }
        if ((bi & 255) == tid) qv[bi >> 8] = -INFINITY;
    }
    __syncthreads();

    if (w == 0) {
        float cv[3];
        int   ci[3];
#pragma unroll
        for (int p = 0; p < 3; p++) {
            int idx = lane + p * 32;
            if (idx < 80) { cv[p] = cand_v[idx]; ci[p] = cand_i[idx]; }
            else          { cv[p] = -INFINITY;   ci[p] = 1 << 30; }
        }
        for (int it = 0; it < 10; it++) {
            float bv = -INFINITY;
            int bi = 1 << 30;
#pragma unroll
            for (int p = 0; p < 3; p++) {
                if (cv[p] > bv || (cv[p] == bv && ci[p] < bi)) { bv = cv[p]; bi = ci[p]; }
            }
#pragma unroll
            for (int o = 16; o > 0; o >>= 1) {
                float ov = __shfl_xor_sync(0xffffffffu, bv, o);
                int   oi = __shfl_xor_sync(0xffffffffu, bi, o);
                if (ov > bv || (ov == bv && oi < bi)) { bv = ov; bi = oi; }
            }
            if (lane == 0) dout[1 + (size_t)r * 10 + it] = (float)bi;
#pragma unroll
            for (int p = 0; p < 3; p++)
                if (ci[p] == bi) { cv[p] = -INFINITY; ci[p] = 1 << 30; }
        }
    }
}

// ---------------- deterministic loss reduction (double) ----------------
__global__ void __launch_bounds__(256) loss_kernel(float* __restrict__ dout) {
    __shared__ double s[256];
    int tid = threadIdx.x;
    double a = 0.0;
    for (int i = 0; i < 32; i++) a += (double)g_rowloss[tid * 32 + i];
    s[tid] = a;
    __syncthreads();
    for (int o = 128; o > 0; o >>= 1) {
        if (tid < o) s[tid] += s[tid + o];
        __syncthreads();
    }
    if (tid == 0) dout[0] = (float)(s[0] / 8192.0);
}

extern "C" void kernel_launch(void* const* d_in, const int* in_sizes, int n_in,
                              void* d_out, int out_size) {
    const int*   pc        = (const int*)d_in[0];
    const int*   delta     = (const int*)d_in[1];
    const int*   clusters  = (const int*)d_in[2];
    const int*   target    = (const int*)d_in[3];
    const float* h0        = (const float*)d_in[4];
    const float* c0        = (const float*)d_in[5];
    const float* pc_emb    = (const float*)d_in[6];
    const float* delta_emb = (const float*)d_in[7];
    const float* w_ih0     = (const float*)d_in[8];
    const float* w_hh0     = (const float*)d_in[9];
    const float* b_ih0     = (const float*)d_in[10];
    const float* b_hh0     = (const float*)d_in[11];
    const float* w_ih1     = (const float*)d_in[12];
    const float* w_hh1     = (const float*)d_in[13];
    const float* b_ih1     = (const float*)d_in[14];
    const float* b_hh1     = (const float*)d_in[15];
    const float* Wc        = (const float*)d_in[16];
    const float* bc        = (const float*)d_in[17];
    float* out = (float*)d_out;

    static int smem_set = 0;
    int lstm_smem = 24960 * 4;
    if (!smem_set) {
        cudaFuncSetAttribute(lstm_kernel, cudaFuncAttributeMaxDynamicSharedMemorySize, lstm_smem);
        smem_set = 1;
    }

    float* g_Y0p = nullptr; float* g_Y1p = nullptr;
    cudaGetSymbolAddress((void**)&g_Y0p, g_Y0);
    cudaGetSymbolAddress((void**)&g_Y1p, g_Y1);

    init_kernel<<<128, 256>>>(h0);
    embed_kernel<<<TB_, 128>>>(pc, delta, pc_emb, delta_emb);
    gemm_ih_kernel<<<dim3(16, 64), 256>>>(0, w_ih0);
    lstm_kernel<<<128, 256, lstm_smem>>>(w_hh0, c0, 0, 0, g_Y0p, out, b_ih0, b_hh0);
    gemm_ih_kernel<<<dim3(16, 64), 256>>>(1, w_ih1);
    lstm_kernel<<<128, 256, lstm_smem>>>(w_hh1, c0 + (size_t)B_ * H_, 1, 1, g_Y1p, out, b_ih1, b_hh1);
    logits_kernel<<<dim3(16, 256), 256>>>(clusters, Wc, bc);
    softmax_topk_kernel<<<TB_, 256>>>(target, out);
    loss_kernel<<<1, 256>>>(out);
}